// round 5
// baseline (speedup 1.0000x reference)
#include <cuda_runtime.h>

// out[t, 0, :] = inputs[t, :]
// out[t, l, :] = memory[l, :]  for l in [1, 64)
// T=2048, L=64, D=1024 (fp32). 512 MB pure-write kernel.
//
// TLB/page-sequential schedule: each grid-y chunk is TT=8 t-rows = exactly one
// 2 MB page. Grid (x=l fast, y=chunk) so the 64 blocks of a chunk fully retire
// one page before the wave advances -> resident wave spans ~19 pages (TLB has
// 128 entries), and the chip-wide store stream is page-sequential for HBM
// row-buffer locality. l>=1 rows are t-invariant: register-held, pure
// streaming stores. l==0 copies inputs with streaming loads.

constexpr int T  = 2048;
constexpr int L  = 64;
constexpr int D  = 1024;
constexpr int D4 = D / 4;            // 256 float4 per row -> 256 threads
constexpr int ROW4 = L * D4;         // float4 per t (256 KB per t)
constexpr int TT = 8;                // t-values per block (2 MB = 1 page)
constexpr int CH = T / TT;           // 256 chunks along t

__global__ __launch_bounds__(256, 8)
void sliding_window_memory_kernel(const float4* __restrict__ inp,
                                  const float4* __restrict__ mem,
                                  float4* __restrict__ out) {
    const int l   = blockIdx.x;          // 0..63  (fast dim: one page/chunk)
    const int t0  = blockIdx.y * TT;
    const int tid = threadIdx.x;         // float4 column 0..255

    if (l == 0) {
        // slot 0 depends on t: copy inputs[t0..t0+TT), streaming reads
        const float4* ip = inp + (size_t)t0 * D4 + tid;
        float4*       op = out + (size_t)t0 * ROW4 + tid;
        #pragma unroll
        for (int i = 0; i < TT; ++i) {
            __stcs(op, __ldcs(ip));
            ip += D4;
            op += ROW4;
        }
    } else {
        // slots 1..63: t-invariant row -> register-held, pure store stream
        const float4 v = __ldg(mem + (size_t)l * D4 + tid);
        float4* op = out + (size_t)t0 * ROW4 + (size_t)l * D4 + tid;
        #pragma unroll
        for (int i = 0; i < TT; ++i) {
            __stcs(op, v);
            op += ROW4;
        }
    }
}

extern "C" void kernel_launch(void* const* d_in, const int* in_sizes, int n_in,
                              void* d_out, int out_size) {
    const float4* inp = (const float4*)d_in[0];   // [T, D] fp32
    const float4* mem = (const float4*)d_in[1];   // [L, D] fp32
    float4* out = (float4*)d_out;                 // [T, L, D] fp32

    dim3 grid(L, CH);
    sliding_window_memory_kernel<<<grid, 256>>>(inp, mem, out);
}